// round 3
// baseline (speedup 1.0000x reference)
#include <cuda_runtime.h>

// CRF forward log-partition. B=512 batches, T=512 steps, L=64 tags.
// Strategy:
//  - E[n][p] = exp(trans[n][p]) precomputed into registers (kills L^2 exps/step).
//  - Per step: e[p] = exp2(fv2[p] - Msc); s[n] = sum_p e[p]*E[n][p] (packed f32x2 FMA);
//    fv2[n] = Msc + log2(s[n]) + emit*log2e.  (base-2 scaled domain throughout)
//  - Msc = global max of fv2 lagged by 2 steps (scale-invariance of lse), so only
//    ONE __syncthreads per step (publishes e-vector + per-warp maxes together).
//  - 128 threads/block = 1 batch row: thread (n,h) owns half (32) of E row n.
//  - Emissions prefetched distance 2.

#define LOG2E 1.4426950408889634f
#define LN2   0.6931471805599453f

constexpr int L  = 64;
constexpr int TT = 512;

static __device__ __forceinline__ float ex2f(float x) {
    float r;
    asm("ex2.approx.ftz.f32 %0, %1;" : "=f"(r) : "f"(x));
    return r;
}
static __device__ __forceinline__ float lg2f(float x) {
    float r;
    asm("lg2.approx.ftz.f32 %0, %1;" : "=f"(r) : "f"(x));
    return r;
}

static __device__ __forceinline__ unsigned long long pk2(float lo, float hi) {
    unsigned long long r;
    asm("mov.b64 %0, {%1, %2};" : "=l"(r) : "f"(lo), "f"(hi));
    return r;
}
static __device__ __forceinline__ void upk2(unsigned long long v, float& lo, float& hi) {
    asm("mov.b64 {%0, %1}, %2;" : "=f"(lo), "=f"(hi) : "l"(v));
}
static __device__ __forceinline__ unsigned long long ffma2(
    unsigned long long a, unsigned long long b, unsigned long long c) {
    unsigned long long d;
    asm("fma.rn.f32x2 %0, %1, %2, %3;" : "=l"(d) : "l"(a), "l"(b), "l"(c));
    return d;
}
static __device__ __forceinline__ unsigned long long fadd2(
    unsigned long long a, unsigned long long b) {
    unsigned long long d;
    asm("add.rn.f32x2 %0, %1, %2;" : "=l"(d) : "l"(a), "l"(b));
    return d;
}

__global__ __launch_bounds__(128, 4) void crf_fwd(
    const float* __restrict__ emis,   // [B, T, L]
    const float* __restrict__ trans,  // [L, L]  trans[next*L + prev]
    float* __restrict__ out)          // [B]
{
    const int b    = blockIdx.x;
    const int tid  = threadIdx.x;
    const int n    = tid >> 1;   // tag 0..63
    const int h    = tid & 1;    // half of prev-dimension
    const int w    = tid >> 5;   // warp 0..3
    const unsigned FULL = 0xffffffffu;

    __shared__ __align__(16) float e_sh[2][L];
    __shared__ __align__(16) float red_sh[2][4];

    // ---- E row half into registers: exp(trans[n][h*32 .. h*32+31]), packed pairs ----
    unsigned long long E2[16];
    {
        const float4* trow = reinterpret_cast<const float4*>(trans + n * L + h * 32);
        #pragma unroll
        for (int j = 0; j < 8; j++) {
            float4 v = trow[j];
            // exp(-10000) underflows to exactly 0 -> blocked transitions contribute 0.
            E2[2 * j]     = pk2(__expf(v.x), __expf(v.y));
            E2[2 * j + 1] = pk2(__expf(v.z), __expf(v.w));
        }
    }
    // terminal transition into STOP, base-2 scaled
    const float tstop = trans[(L - 1) * L + n] * LOG2E;

    // ---- init forward var (base-2 domain): START (= L-2) gets 0, rest NEG*log2e ----
    float fv  = (n == L - 2) ? 0.0f : (-10000.0f * LOG2E);
    float Msc = 0.0f;              // scale estimate (exact max of fv_0)
    float wm  = fv;                // warp max of current fv (tags dup'd on h -> skip xor 1)
    #pragma unroll
    for (int o = 16; o >= 2; o >>= 1) wm = fmaxf(wm, __shfl_xor_sync(FULL, wm, o));

    // ---- emissions: thread reads emis[b][t][n]; prefetch distance 2 ----
    const float* eptr = emis + (size_t)b * (TT * L) + n;
    float em_a = __ldg(eptr);
    float em_b = __ldg(eptr + L);

    int buf = 0;
    for (int t = 0; t < TT; t++) {
        // publish e-vector and per-warp maxes through ONE barrier
        float e = ex2f(fv - Msc);
        if (h == 0)          e_sh[buf][n]   = e;
        if ((tid & 31) == 0) red_sh[buf][w] = wm;
        __syncthreads();

        // prefetch emissions for t+2 (covers ~577cy DRAM latency)
        float em_c = (t + 2 < TT) ? __ldg(eptr + (t + 2) * L) : 0.0f;

        // global max of fv_{t-1} -> becomes scale at step t+1 (lag-2 overall, bounded drift)
        float4 wv = *reinterpret_cast<const float4*>(red_sh[buf]);
        float Mnext = fmaxf(fmaxf(wv.x, wv.y), fmaxf(wv.z, wv.w));

        // half matvec: s_half = sum over 32 prev tags, packed f32x2, 4 acc chains
        unsigned long long a0 = 0ull, a1 = 0ull, a2 = 0ull, a3 = 0ull;
        const ulonglong2* ev = reinterpret_cast<const ulonglong2*>(&e_sh[buf][h * 32]);
        #pragma unroll
        for (int j = 0; j < 4; j++) {
            ulonglong2 q0 = ev[2 * j];
            ulonglong2 q1 = ev[2 * j + 1];
            a0 = ffma2(q0.x, E2[4 * j],     a0);
            a1 = ffma2(q0.y, E2[4 * j + 1], a1);
            a2 = ffma2(q1.x, E2[4 * j + 2], a2);
            a3 = ffma2(q1.y, E2[4 * j + 3], a3);
        }
        unsigned long long at = fadd2(fadd2(a0, a1), fadd2(a2, a3));
        float lo, hi;
        upk2(at, lo, hi);
        float s = lo + hi;
        // combine with partner half (lane xor 1 = same tag, other h)
        s += __shfl_xor_sync(FULL, s, 1);

        // fv_t = Msc + log2(s) + emit*log2e  (exact lse, Msc cancels)
        fv = fmaf(em_a, LOG2E, Msc + lg2f(s));
        em_a = em_b; em_b = em_c;
        Msc  = Mnext;

        // warp max of new fv (pipelined; published at next step's barrier)
        wm = fv;
        #pragma unroll
        for (int o = 16; o >= 2; o >>= 1) wm = fmaxf(wm, __shfl_xor_sync(FULL, wm, o));

        buf ^= 1;
    }

    // ---- terminal: lse over tags of fv + trans[STOP][n], back to natural log ----
    float x  = fv + tstop;
    float xm = x;
    #pragma unroll
    for (int o = 16; o >= 2; o >>= 1) xm = fmaxf(xm, __shfl_xor_sync(FULL, xm, o));
    // NOTE: last in-loop reads touched red_sh[1] (t=511 -> buf=1); writing red_sh[0]
    // here is race-free, and red_sh[1] below is written only after the barrier.
    if ((tid & 31) == 0) red_sh[0][w] = xm;
    __syncthreads();
    float4 mv = *reinterpret_cast<const float4*>(red_sh[0]);
    float M = fmaxf(fmaxf(mv.x, mv.y), fmaxf(mv.z, mv.w));

    float term = (h == 0) ? ex2f(x - M) : 0.0f;   // zero dup half to avoid double count
    #pragma unroll
    for (int o = 16; o >= 1; o >>= 1) term += __shfl_xor_sync(FULL, term, o);
    if ((tid & 31) == 0) red_sh[1][w] = term;
    __syncthreads();
    if (tid == 0) {
        float ss = red_sh[1][0] + red_sh[1][1] + red_sh[1][2] + red_sh[1][3];
        out[b] = (M + lg2f(ss)) * LN2;
    }
}

extern "C" void kernel_launch(void* const* d_in, const int* in_sizes, int n_in,
                              void* d_out, int out_size) {
    const float* emis  = (const float*)d_in[0];   // [B, T, L] float32
    const float* trans = (const float*)d_in[1];   // [L, L] float32
    float* out = (float*)d_out;                   // [B] float32
    int B = in_sizes[0] / (TT * L);
    crf_fwd<<<B, 128>>>(emis, trans, out);
}

// round 4
// speedup vs baseline: 1.5492x; 1.5492x over previous
#include <cuda_runtime.h>

// CRF forward log-partition. B=512, T=512, L=64.
// Linear-domain scan: v_{t+1}[n] = (sum_p E[n,p] v_t[p]) * exp(emit_t[n]) * scale
//  - E = exp(transitions) in registers; masked entries exp(-10000) -> exactly 0.
//  - exp(emit) via MUFU at prefetch time (distance 2) -> off the critical path.
//  - Power-of-2 renorm every 4 steps (exponent-bit trick), published through the
//    per-step barrier with 1-step lag; log2-scale accumulated in an int.
//  - Layout: 128 thr/block = 1 batch. thread (g,q): tags {g, g+32}, prev quarter
//    [16q,16q+16). Register tiling (2 tags/thread) halves smem read traffic.
//  - v_sh padded: quarter q at offset 20*q floats -> conflict-free LDS.128.

#define LOG2E 1.4426950408889634f
#define LN2   0.6931471805599453f

constexpr int L  = 64;
constexpr int TT = 512;

static __device__ __forceinline__ float ex2f(float x) {
    float r; asm("ex2.approx.ftz.f32 %0, %1;" : "=f"(r) : "f"(x)); return r;
}
static __device__ __forceinline__ float lg2f(float x) {
    float r; asm("lg2.approx.ftz.f32 %0, %1;" : "=f"(r) : "f"(x)); return r;
}
static __device__ __forceinline__ unsigned long long pk2(float lo, float hi) {
    unsigned long long r;
    asm("mov.b64 %0, {%1, %2};" : "=l"(r) : "f"(lo), "f"(hi)); return r;
}
static __device__ __forceinline__ void upk2(unsigned long long v, float& lo, float& hi) {
    asm("mov.b64 {%0, %1}, %2;" : "=f"(lo), "=f"(hi) : "l"(v));
}
static __device__ __forceinline__ unsigned long long ffma2(
    unsigned long long a, unsigned long long b, unsigned long long c) {
    unsigned long long d;
    asm("fma.rn.f32x2 %0, %1, %2, %3;" : "=l"(d) : "l"(a), "l"(b), "l"(c)); return d;
}
static __device__ __forceinline__ unsigned long long fadd2(
    unsigned long long a, unsigned long long b) {
    unsigned long long d;
    asm("add.rn.f32x2 %0, %1, %2;" : "=l"(d) : "l"(a), "l"(b)); return d;
}

// padded quarter stride: 20 floats (80B) -> quarter bases hit disjoint banks
constexpr int VPAD = 20;

__global__ __launch_bounds__(128, 4) void crf_fwd(
    const float* __restrict__ emis,   // [B, T, L]
    const float* __restrict__ trans,  // [L, L]  trans[next*L + prev]
    float* __restrict__ out)          // [B]
{
    const int b   = blockIdx.x;
    const int tid = threadIdx.x;
    const int g   = tid >> 2;      // 0..31  -> tags g, g+32
    const int q   = tid & 3;       // prev quarter
    const int w   = tid >> 5;      // warp 0..3
    const int n0  = g, n1 = g + 32;
    const unsigned FULL = 0xffffffffu;

    __shared__ __align__(16) float v_sh[2][4 * VPAD];
    __shared__ __align__(16) float red_sh[4];
    __shared__ __align__(16) float sum_sh[4];

    // ---- E rows (2 tags x 16 prevs) into packed-pair registers ----
    unsigned long long E0[8], E1[8];
    {
        const float4* r0 = reinterpret_cast<const float4*>(trans + n0 * L + q * 16);
        const float4* r1 = reinterpret_cast<const float4*>(trans + n1 * L + q * 16);
        #pragma unroll
        for (int j = 0; j < 4; j++) {
            float4 a = r0[j];
            E0[2 * j]     = pk2(__expf(a.x), __expf(a.y));
            E0[2 * j + 1] = pk2(__expf(a.z), __expf(a.w));
            float4 c = r1[j];
            E1[2 * j]     = pk2(__expf(c.x), __expf(c.y));
            E1[2 * j + 1] = pk2(__expf(c.z), __expf(c.w));
        }
    }
    const float Es0 = __expf(trans[(L - 1) * L + n0]);   // exp(trans[STOP][n])
    const float Es1 = __expf(trans[(L - 1) * L + n1]);

    // ---- init shared: v0 = delta(START), renorm seed 1.0 ----
    if (tid < L) {
        int blk = tid >> 4, off = tid & 15;
        v_sh[0][blk * VPAD + off] = (tid == L - 2) ? 1.0f : 0.0f;
    }
    if (tid < 4) red_sh[tid] = 1.0f;

    // ---- emission pipeline: exp(emit) computed at prefetch (distance 2) ----
    const float* e0 = emis + (size_t)b * (TT * L) + n0;
    const float* e1 = e0 + 32;
    float eA0 = ex2f(__ldg(e0) * LOG2E);
    float eA1 = ex2f(__ldg(e1) * LOG2E);
    float eB0 = ex2f(__ldg(e0 + L) * LOG2E);
    float eB1 = ex2f(__ldg(e1 + L) * LOG2E);

    int   acc2 = 0;        // accumulated log2 of removed scales (same on all threads)
    float v0 = 0.0f, v1 = 0.0f;
    int   buf = 0;
    __syncthreads();

    #pragma unroll 1
    for (int it = 0; it < TT / 4; ++it) {
        #pragma unroll
        for (int s = 0; s < 4; ++s) {
            const int t = it * 4 + s;

            float f0 = eA0, f1 = eA1;
            if (s == 0) {
                // apply renorm measured at previous slot 3 (lag 1 step)
                float4 rv = *reinterpret_cast<const float4*>(red_sh);
                float m = fmaxf(fmaxf(rv.x, rv.y), fmaxf(rv.z, rv.w));
                int ei = (int)((__float_as_uint(m) >> 23) & 0xff);
                float scale = __uint_as_float((unsigned)(253 - ei) << 23); // 2^(126-ei)
                acc2 += ei - 126;
                f0 *= scale; f1 *= scale;
            }

            // ---- matvec quarter: 2 tags x 16 prevs, packed f32x2 ----
            const ulonglong2* vv =
                reinterpret_cast<const ulonglong2*>(&v_sh[buf][q * VPAD]);
            ulonglong2 p0 = vv[0], p1 = vv[1], p2 = vv[2], p3 = vv[3];

            unsigned long long c00 = ffma2(p0.x, E0[0], 0ull);
            unsigned long long c01 = ffma2(p0.y, E0[1], 0ull);
            unsigned long long c10 = ffma2(p0.x, E1[0], 0ull);
            unsigned long long c11 = ffma2(p0.y, E1[1], 0ull);
            c00 = ffma2(p1.x, E0[2], c00);  c01 = ffma2(p1.y, E0[3], c01);
            c10 = ffma2(p1.x, E1[2], c10);  c11 = ffma2(p1.y, E1[3], c11);
            c00 = ffma2(p2.x, E0[4], c00);  c01 = ffma2(p2.y, E0[5], c01);
            c10 = ffma2(p2.x, E1[4], c10);  c11 = ffma2(p2.y, E1[5], c11);
            c00 = ffma2(p3.x, E0[6], c00);  c01 = ffma2(p3.y, E0[7], c01);
            c10 = ffma2(p3.x, E1[6], c10);  c11 = ffma2(p3.y, E1[7], c11);

            float s0, s1;
            { float lo, hi; upk2(fadd2(c00, c01), lo, hi); s0 = lo + hi; }
            { float lo, hi; upk2(fadd2(c10, c11), lo, hi); s1 = lo + hi; }

            // combine across the 4 prev-quarters (lanes q = tid&3)
            s0 += __shfl_xor_sync(FULL, s0, 1);
            s1 += __shfl_xor_sync(FULL, s1, 1);
            s0 += __shfl_xor_sync(FULL, s0, 2);
            s1 += __shfl_xor_sync(FULL, s1, 2);

            v0 = s0 * f0;
            v1 = s1 * f1;

            if (q == 0) {
                // padded store: tag n -> (n>>4)*VPAD + (n&15)
                v_sh[buf ^ 1][(n0 >> 4) * VPAD + (n0 & 15)] = v0;
                v_sh[buf ^ 1][(n1 >> 4) * VPAD + (n1 & 15)] = v1;
            }

            if (s == 3) {
                // measure max(v) of THIS step only; publish per-warp
                float wm = fmaxf(v0, v1);
                #pragma unroll
                for (int o = 16; o >= 1; o >>= 1)
                    wm = fmaxf(wm, __shfl_xor_sync(FULL, wm, o));
                if ((tid & 31) == 0) red_sh[w] = wm;
            }

            // prefetch emissions for t+2, exp off the critical path
            {
                int tp = (t + 2 < TT) ? t + 2 : TT - 1;
                float r0 = __ldg(e0 + (size_t)tp * L);
                float r1 = __ldg(e1 + (size_t)tp * L);
                eA0 = eB0; eA1 = eB1;
                eB0 = ex2f(r0 * LOG2E);
                eB1 = ex2f(r1 * LOG2E);
            }

            __syncthreads();
            buf ^= 1;
        }
    }

    // ---- terminal: log(sum_n v[n]*exp(trans[STOP][n])) + acc2*ln2 ----
    float term = (q == 0) ? fmaf(v1, Es1, v0 * Es0) : 0.0f;
    #pragma unroll
    for (int o = 16; o >= 1; o >>= 1) term += __shfl_xor_sync(FULL, term, o);
    if ((tid & 31) == 0) sum_sh[w] = term;
    __syncthreads();
    if (tid == 0) {
        float tot = sum_sh[0] + sum_sh[1] + sum_sh[2] + sum_sh[3];
        out[b] = (lg2f(tot) + (float)acc2) * LN2;
    }
}

extern "C" void kernel_launch(void* const* d_in, const int* in_sizes, int n_in,
                              void* d_out, int out_size) {
    const float* emis  = (const float*)d_in[0];   // [B, T, L] float32
    const float* trans = (const float*)d_in[1];   // [L, L] float32
    float* out = (float*)d_out;                   // [B] float32
    int B = in_sizes[0] / (TT * L);
    crf_fwd<<<B, 128>>>(emis, trans, out);
}